// round 15
// baseline (speedup 1.0000x reference)
#include <cuda_runtime.h>
#include <cuda_bf16.h>
#include <cstdint>

// ---------------------------------------------------------------------------
// Problem constants (fixed by the dataset)
// ---------------------------------------------------------------------------
#define NNODES 50000
#define MAXF   1536
#define MAXE   400000
#define NSB    ((NNODES + 1023) / 1024)

// Scratch (allocation-free: __device__ globals)
__device__ float g_B0[(size_t)NNODES * MAXF];
__device__ float g_B1[(size_t)NNODES * MAXF];
__device__ __nv_bfloat16 g_Ahi[(size_t)NNODES * MAXF];
__device__ __nv_bfloat16 g_Alo[(size_t)NNODES * MAXF];
__device__ __nv_bfloat16 g_Bhi[(size_t)NNODES * MAXF];
__device__ __nv_bfloat16 g_Blo[(size_t)NNODES * MAXF];
__device__ __nv_bfloat16 g_Whi[(size_t)MAXF * MAXF];
__device__ __nv_bfloat16 g_Wlo[(size_t)MAXF * MAXF];
__device__ float g_dinv[NNODES];
__device__ int   g_cnt[NNODES];
__device__ int   g_rowptr[NNODES + 1];
__device__ int   g_next[NNODES];
__device__ int   g_csrc[MAXE];
__device__ float g_cw[MAXE];
__device__ int   g_btot[64];

__device__ __forceinline__ uint32_t smem_u32(const void* p) {
    uint32_t a;
    asm("{ .reg .u64 t; cvta.to.shared.u64 t, %1; cvt.u32.u64 %0, t; }" : "=r"(a) : "l"(p));
    return a;
}

// ---------------------------------------------------------------------------
// CSR build
// ---------------------------------------------------------------------------
__global__ void zeroi_kernel(int* __restrict__ p, int n) {
    int i = blockIdx.x * blockDim.x + threadIdx.x;
    if (i < n) p[i] = 0;
}

__global__ void hist_kernel(const int* __restrict__ dst, int* __restrict__ cnt, int E) {
    int e = blockIdx.x * blockDim.x + threadIdx.x;
    if (e < E) atomicAdd(&cnt[dst[e]], 1);
}

// Blocked scan, pass 1: per-block exclusive scan, block totals, dinv.
__global__ __launch_bounds__(1024) void scan1_kernel(const int* __restrict__ cnt,
                                                     int* __restrict__ excl,
                                                     float* __restrict__ dinv) {
    __shared__ int wsum[32];
    const int tid = threadIdx.x, lane = tid & 31, wid = tid >> 5;
    const int i = blockIdx.x * 1024 + tid;
    int v = (i < NNODES) ? cnt[i] : 0;
    if (i < NNODES) dinv[i] = rsqrtf((float)v + 1.0f);
    int x = v;
    #pragma unroll
    for (int off = 1; off < 32; off <<= 1) {
        int t = __shfl_up_sync(0xFFFFFFFFu, x, off);
        if (lane >= off) x += t;
    }
    if (lane == 31) wsum[wid] = x;
    __syncthreads();
    if (wid == 0) {
        int y = wsum[lane];
        #pragma unroll
        for (int off = 1; off < 32; off <<= 1) {
            int t = __shfl_up_sync(0xFFFFFFFFu, y, off);
            if (lane >= off) y += t;
        }
        wsum[lane] = y;
    }
    __syncthreads();
    const int woff = (wid > 0) ? wsum[wid - 1] : 0;
    if (i < NNODES) excl[i] = x + woff - v;
    if (tid == 1023) g_btot[blockIdx.x] = x + woff;
}

// pass 2: scan the NSB block totals (tiny), write rowptr[NNODES]
__global__ void scan2_kernel(int* __restrict__ rowptr) {
    int run = 0;
    for (int b = 0; b < NSB; b++) { int t = g_btot[b]; g_btot[b] = run; run += t; }
    rowptr[NNODES] = run;
}

// pass 3: add block offsets, produce rowptr + next
__global__ __launch_bounds__(1024) void scan3_kernel(int* __restrict__ rowptr,
                                                     int* __restrict__ nxt) {
    const int i = blockIdx.x * 1024 + threadIdx.x;
    if (i < NNODES) {
        int v = rowptr[i] + g_btot[blockIdx.x];
        rowptr[i] = v;
        nxt[i] = v;
    }
}

__global__ void fill_kernel(const int* __restrict__ src, const int* __restrict__ dst,
                            const float* __restrict__ dinv, int* __restrict__ nxt,
                            int* __restrict__ csrc, float* __restrict__ cw, int E) {
    int e = blockIdx.x * blockDim.x + threadIdx.x;
    if (e >= E) return;
    int s = src[e], d = dst[e];
    int pos = atomicAdd(&nxt[d], 1);
    csrc[pos] = s;
    cw[pos] = dinv[s] * dinv[d];
}

// ---------------------------------------------------------------------------
// bf16 split helpers
// ---------------------------------------------------------------------------
__device__ __forceinline__ void store_split4_cs(__nv_bfloat16* hi, __nv_bfloat16* lo,
                                                size_t idx, float4 a) {
    __nv_bfloat16 h0 = __float2bfloat16(a.x), h1 = __float2bfloat16(a.y);
    __nv_bfloat16 h2 = __float2bfloat16(a.z), h3 = __float2bfloat16(a.w);
    __nv_bfloat16 l0 = __float2bfloat16(a.x - __bfloat162float(h0));
    __nv_bfloat16 l1 = __float2bfloat16(a.y - __bfloat162float(h1));
    __nv_bfloat16 l2 = __float2bfloat16(a.z - __bfloat162float(h2));
    __nv_bfloat16 l3 = __float2bfloat16(a.w - __bfloat162float(h3));
    __nv_bfloat162 hv0 = __halves2bfloat162(h0, h1), hv1 = __halves2bfloat162(h2, h3);
    __nv_bfloat162 lv0 = __halves2bfloat162(l0, l1), lv1 = __halves2bfloat162(l2, l3);
    asm volatile("st.global.cs.v2.b32 [%0], {%1,%2};"
                 :: "l"(hi + idx), "r"(*(uint32_t*)&hv0), "r"(*(uint32_t*)&hv1) : "memory");
    asm volatile("st.global.cs.v2.b32 [%0], {%1,%2};"
                 :: "l"(lo + idx), "r"(*(uint32_t*)&lv0), "r"(*(uint32_t*)&lv1) : "memory");
}

__device__ __forceinline__ void store_split2(__nv_bfloat16* hi, __nv_bfloat16* lo,
                                             size_t idx, float a, float b) {
    __nv_bfloat16 h0 = __float2bfloat16(a), h1 = __float2bfloat16(b);
    __nv_bfloat16 l0 = __float2bfloat16(a - __bfloat162float(h0));
    __nv_bfloat16 l1 = __float2bfloat16(b - __bfloat162float(h1));
    __nv_bfloat162 hv = __halves2bfloat162(h0, h1);
    __nv_bfloat162 lv = __halves2bfloat162(l0, l1);
    *(uint32_t*)(hi + idx) = *(uint32_t*)&hv;
    *(uint32_t*)(lo + idx) = *(uint32_t*)&lv;
}

// ---------------------------------------------------------------------------
// Fused CSR gather over a column chunk
// ---------------------------------------------------------------------------
__global__ void gather_kernel(const float* __restrict__ h, const float* __restrict__ bias,
                              float* __restrict__ outf,
                              __nv_bfloat16* __restrict__ hi, __nv_bfloat16* __restrict__ lo,
                              int F, int fbase, int do_relu)
{
    const int node = blockIdx.x;
    const int f0 = fbase + threadIdx.x * 4;
    const int rs = g_rowptr[node], re = g_rowptr[node + 1];
    const float di = g_dinv[node];
    const float d2 = di * di;

    float4 acc = *(const float4*)(h + (size_t)node * F + f0);
    acc.x *= d2; acc.y *= d2; acc.z *= d2; acc.w *= d2;
    if (bias) {
        float4 bb = *(const float4*)(bias + f0);
        acc.x += bb.x; acc.y += bb.y; acc.z += bb.z; acc.w += bb.w;
    }
    for (int e = rs; e < re; e++) {
        const int s = g_csrc[e];
        const float w = g_cw[e];
        float4 v = *(const float4*)(h + (size_t)s * F + f0);
        acc.x += v.x * w; acc.y += v.y * w; acc.z += v.z * w; acc.w += v.w * w;
    }
    if (do_relu) {
        acc.x = fmaxf(acc.x, 0.f); acc.y = fmaxf(acc.y, 0.f);
        acc.z = fmaxf(acc.z, 0.f); acc.w = fmaxf(acc.w, 0.f);
    }
    const size_t idx = (size_t)node * F + f0;
    if (outf) {
        asm volatile("st.global.cs.v4.f32 [%0], {%1,%2,%3,%4};"
                     :: "l"(outf + idx), "f"(acc.x), "f"(acc.y), "f"(acc.z), "f"(acc.w)
                     : "memory");
    }
    if (hi) store_split4_cs(hi, lo, idx, acc);
}

// ---------------------------------------------------------------------------
// W [K,N] fp32 -> Wt_hi/Wt_lo [N,K] bf16 (transpose + split)
// ---------------------------------------------------------------------------
__global__ void wconv_kernel(const float* __restrict__ W, __nv_bfloat16* __restrict__ Thi,
                             __nv_bfloat16* __restrict__ Tlo, int K, int N) {
    int idx = blockIdx.x * blockDim.x + threadIdx.x;
    if (idx >= K * N) return;
    int k = idx / N, n = idx - k * N;
    float w = W[idx];
    __nv_bfloat16 h = __float2bfloat16(w);
    Thi[(size_t)n * K + k] = h;
    Tlo[(size_t)n * K + k] = __float2bfloat16(w - __bfloat162float(h));
}

// ---------------------------------------------------------------------------
// Final layer: out[node, 0..4] = g[node, :] @ W5[192,5] + b5  (thread per node)
// ---------------------------------------------------------------------------
__global__ __launch_bounds__(256) void out5_kernel(const float* __restrict__ g,
                                                   const float* __restrict__ W5,
                                                   const float* __restrict__ b5,
                                                   float* __restrict__ out)
{
    __shared__ float sW[192 * 5];
    for (int i = threadIdx.x; i < 192 * 5; i += 256) sW[i] = W5[i];
    __syncthreads();
    const int node = blockIdx.x * 256 + threadIdx.x;
    if (node >= NNODES) return;
    float a0 = b5[0], a1 = b5[1], a2 = b5[2], a3 = b5[3], a4 = b5[4];
    const float4* gp = (const float4*)(g + (size_t)node * 192);
    #pragma unroll 4
    for (int k4 = 0; k4 < 48; k4++) {
        float4 v = gp[k4];
        const float* w = &sW[(k4 * 4) * 5];
        a0 += v.x * w[0] + v.y * w[5] + v.z * w[10] + v.w * w[15];
        a1 += v.x * w[1] + v.y * w[6] + v.z * w[11] + v.w * w[16];
        a2 += v.x * w[2] + v.y * w[7] + v.z * w[12] + v.w * w[17];
        a3 += v.x * w[3] + v.y * w[8] + v.z * w[13] + v.w * w[18];
        a4 += v.x * w[4] + v.y * w[9] + v.z * w[14] + v.w * w[19];
    }
    float* op = out + (size_t)node * 5;
    op[0] = a0; op[1] = a1; op[2] = a2; op[3] = a3; op[4] = a4;
}

// ---------------------------------------------------------------------------
// Fused bf16x3 GEMM: C = Ahi*Whi + Alo*Whi + Ahi*Wlo, all 3 passes per chunk.
//   BK=32 chunks, 4-stage cp.async pipeline, ONE __syncthreads per chunk:
//   issue(c+3) writes buffer (c-1)&3 whose readers all passed this iteration's
//   barrier (placed after their compute(c-1)), so no trailing barrier needed.
//   Optional epilogue: out = relu(acc + bias) -> bf16 hi/lo split buffers.
// ---------------------------------------------------------------------------
template<int BNT>
__global__ __launch_bounds__(256)
void gemm3_kernel(const __nv_bfloat16* __restrict__ Ahi, const __nv_bfloat16* __restrict__ Alo,
                  const __nv_bfloat16* __restrict__ Whi, const __nv_bfloat16* __restrict__ Wlo,
                  float* __restrict__ Cf,
                  __nv_bfloat16* __restrict__ Ehi, __nv_bfloat16* __restrict__ Elo,
                  const float* __restrict__ bias,
                  int M, int K, int N, int do_relu)
{
    constexpr int NW = BNT / 32;
    constexpr int STAGE = (256 + 2 * BNT) * 64;     // BK=32 -> 64B rows
    constexpr int OFF_ALO = 128 * 64;
    constexpr int OFF_BHI = 256 * 64;
    constexpr int OFF_BLO = (256 + BNT) * 64;
    constexpr int NCH = (256 + 2 * BNT) * 4 / 256;  // 16B chunks per thread per stage

    extern __shared__ __align__(1024) char smem[];
    const uint32_t sbase = smem_u32(smem);

    const int tid = threadIdx.x, lane = tid & 31, wid = tid >> 5;
    const int wm = (wid & 1) * 64;
    const int wn = (wid >> 1) * (BNT / 4);
    const int m0 = blockIdx.y * 128;
    const int n0 = blockIdx.x * BNT;
    const int kc = K / 32;

    float acc[4][NW][4];
    #pragma unroll
    for (int mi = 0; mi < 4; mi++)
        #pragma unroll
        for (int ni = 0; ni < NW; ni++)
            #pragma unroll
            for (int q = 0; q < 4; q++) acc[mi][ni][q] = 0.f;

    auto issue = [&](int c) {
        const int st = c & 3;
        const int kk = c * 32;
        const uint32_t dstb = sbase + (uint32_t)st * STAGE;
        #pragma unroll
        for (int h = 0; h < NCH; h++) {
            const int idx = tid + h * 256;
            const int r_all = idx >> 2, ch = idx & 3;
            const __nv_bfloat16* base;
            uint32_t roff;
            int r, grow, limit;
            if (r_all < 128)            { base = Ahi; roff = 0;       r = r_all;             grow = m0 + r; limit = M; }
            else if (r_all < 256)       { base = Alo; roff = OFF_ALO; r = r_all - 128;       grow = m0 + r; limit = M; }
            else if (r_all < 256 + BNT) { base = Whi; roff = OFF_BHI; r = r_all - 256;       grow = n0 + r; limit = N; }
            else                        { base = Wlo; roff = OFF_BLO; r = r_all - 256 - BNT; grow = n0 + r; limit = N; }
            const int ok = (grow < limit) ? 16 : 0;
            const int grc = ok ? grow : 0;
            const void* g = base + (size_t)grc * K + kk + ch * 8;
            const uint32_t d = dstb + roff + (uint32_t)r * 64 + (uint32_t)((ch ^ (r & 3)) * 16);
            asm volatile("cp.async.cg.shared.global [%0], [%1], 16, %2;"
                         :: "r"(d), "l"(g), "r"(ok));
        }
        asm volatile("cp.async.commit_group;" ::: "memory");
    };

    auto compute = [&](int st) {
        const uint32_t sAh = sbase + (uint32_t)st * STAGE;
        const uint32_t sAl = sAh + OFF_ALO;
        const uint32_t sBh = sAh + OFF_BHI;
        const uint32_t sBl = sAh + OFF_BLO;
        #pragma unroll
        for (int ks = 0; ks < 2; ks++) {   // two k16 steps in BK=32
            uint32_t ah[4][4], al[4][4], b[NW][2];
            #pragma unroll
            for (int mi = 0; mi < 4; mi++) {
                const int r = wm + mi * 16 + (lane & 15);
                const int ch = ks * 2 + (lane >> 4);
                const uint32_t off = (uint32_t)r * 64 + (uint32_t)((ch ^ (r & 3)) * 16);
                asm volatile("ldmatrix.sync.aligned.m8n8.x4.shared.b16 {%0,%1,%2,%3}, [%4];"
                             : "=r"(ah[mi][0]), "=r"(ah[mi][1]), "=r"(ah[mi][2]), "=r"(ah[mi][3])
                             : "r"(sAh + off));
                asm volatile("ldmatrix.sync.aligned.m8n8.x4.shared.b16 {%0,%1,%2,%3}, [%4];"
                             : "=r"(al[mi][0]), "=r"(al[mi][1]), "=r"(al[mi][2]), "=r"(al[mi][3])
                             : "r"(sAl + off));
            }
            #pragma unroll
            for (int g2 = 0; g2 < NW / 2; g2++) {
                const int r = wn + g2 * 16 + (lane & 7) + ((lane >> 4) << 3);
                const int ch = ks * 2 + ((lane >> 3) & 1);
                const uint32_t off = (uint32_t)r * 64 + (uint32_t)((ch ^ (r & 3)) * 16);
                asm volatile("ldmatrix.sync.aligned.m8n8.x4.shared.b16 {%0,%1,%2,%3}, [%4];"
                             : "=r"(b[g2 * 2][0]), "=r"(b[g2 * 2][1]),
                               "=r"(b[g2 * 2 + 1][0]), "=r"(b[g2 * 2 + 1][1])
                             : "r"(sBh + off));
            }
            #pragma unroll
            for (int mi = 0; mi < 4; mi++)
                #pragma unroll
                for (int ni = 0; ni < NW; ni++) {
                    asm volatile(
                        "mma.sync.aligned.m16n8k16.row.col.f32.bf16.bf16.f32 "
                        "{%0,%1,%2,%3}, {%4,%5,%6,%7}, {%8,%9}, {%0,%1,%2,%3};"
                        : "+f"(acc[mi][ni][0]), "+f"(acc[mi][ni][1]),
                          "+f"(acc[mi][ni][2]), "+f"(acc[mi][ni][3])
                        : "r"(ah[mi][0]), "r"(ah[mi][1]), "r"(ah[mi][2]), "r"(ah[mi][3]),
                          "r"(b[ni][0]), "r"(b[ni][1]));
                }
            #pragma unroll
            for (int mi = 0; mi < 4; mi++)
                #pragma unroll
                for (int ni = 0; ni < NW; ni++) {
                    asm volatile(
                        "mma.sync.aligned.m16n8k16.row.col.f32.bf16.bf16.f32 "
                        "{%0,%1,%2,%3}, {%4,%5,%6,%7}, {%8,%9}, {%0,%1,%2,%3};"
                        : "+f"(acc[mi][ni][0]), "+f"(acc[mi][ni][1]),
                          "+f"(acc[mi][ni][2]), "+f"(acc[mi][ni][3])
                        : "r"(al[mi][0]), "r"(al[mi][1]), "r"(al[mi][2]), "r"(al[mi][3]),
                          "r"(b[ni][0]), "r"(b[ni][1]));
                }
            #pragma unroll
            for (int g2 = 0; g2 < NW / 2; g2++) {
                const int r = wn + g2 * 16 + (lane & 7) + ((lane >> 4) << 3);
                const int ch = ks * 2 + ((lane >> 3) & 1);
                const uint32_t off = (uint32_t)r * 64 + (uint32_t)((ch ^ (r & 3)) * 16);
                asm volatile("ldmatrix.sync.aligned.m8n8.x4.shared.b16 {%0,%1,%2,%3}, [%4];"
                             : "=r"(b[g2 * 2][0]), "=r"(b[g2 * 2][1]),
                               "=r"(b[g2 * 2 + 1][0]), "=r"(b[g2 * 2 + 1][1])
                             : "r"(sBl + off));
            }
            #pragma unroll
            for (int mi = 0; mi < 4; mi++)
                #pragma unroll
                for (int ni = 0; ni < NW; ni++) {
                    asm volatile(
                        "mma.sync.aligned.m16n8k16.row.col.f32.bf16.bf16.f32 "
                        "{%0,%1,%2,%3}, {%4,%5,%6,%7}, {%8,%9}, {%0,%1,%2,%3};"
                        : "+f"(acc[mi][ni][0]), "+f"(acc[mi][ni][1]),
                          "+f"(acc[mi][ni][2]), "+f"(acc[mi][ni][3])
                        : "r"(ah[mi][0]), "r"(ah[mi][1]), "r"(ah[mi][2]), "r"(ah[mi][3]),
                          "r"(b[ni][0]), "r"(b[ni][1]));
                }
        }
    };

    // 4-stage pipeline, single barrier per chunk.
    issue(0);
    if (kc > 1) issue(1);
    if (kc > 2) issue(2);
    for (int c = 0; c < kc; c++) {
        if (c + 2 < kc) {
            asm volatile("cp.async.wait_group 2;" ::: "memory");
        } else if (c + 1 < kc) {
            asm volatile("cp.async.wait_group 1;" ::: "memory");
        } else {
            asm volatile("cp.async.wait_group 0;" ::: "memory");
        }
        __syncthreads();
        if (c + 3 < kc) issue(c + 3);
        compute(c & 3);
    }

    // epilogue
    #pragma unroll
    for (int mi = 0; mi < 4; mi++) {
        const int r0 = m0 + wm + mi * 16 + (lane >> 2);
        #pragma unroll
        for (int ni = 0; ni < NW; ni++) {
            const int col = n0 + wn + ni * 8 + 2 * (lane & 3);
            if (col >= N) continue;
            float bx = 0.f, by = 0.f;
            if (bias) { float2 bb = *(const float2*)(bias + col); bx = bb.x; by = bb.y; }
            #pragma unroll
            for (int half = 0; half < 2; half++) {
                const int r = r0 + half * 8;
                if (r >= M) continue;
                float vx = acc[mi][ni][half * 2 + 0] + bx;
                float vy = acc[mi][ni][half * 2 + 1] + by;
                if (do_relu) { vx = fmaxf(vx, 0.f); vy = fmaxf(vy, 0.f); }
                const size_t idx = (size_t)r * N + col;
                if (Cf) *(float2*)(Cf + idx) = make_float2(vx, vy);
                if (Ehi) store_split2(Ehi, Elo, idx, vx, vy);
            }
        }
    }
}

// ---------------------------------------------------------------------------
// kernel_launch
// ---------------------------------------------------------------------------
extern "C" void kernel_launch(void* const* d_in, const int* in_sizes, int n_in,
                              void* d_out, int out_size)
{
    const float* x   = (const float*)d_in[0];
    const int*   ei  = (const int*)d_in[1];
    const int    E   = in_sizes[1] / 2;
    const int*   src = ei;
    const int*   dst = ei + E;

    const float* W[5];
    const float* b[5];
    for (int i = 0; i < 5; i++) {
        W[i] = (const float*)d_in[2 + 2 * i];
        b[i] = (const float*)d_in[3 + 2 * i];
    }

    float *B0, *B1, *dinv, *cw;
    int *cnt, *rowptr, *nxt, *csrc;
    __nv_bfloat16 *Ahi, *Alo, *Bhi, *Blo, *Whi, *Wlo;
    cudaGetSymbolAddress((void**)&B0,     g_B0);
    cudaGetSymbolAddress((void**)&B1,     g_B1);
    cudaGetSymbolAddress((void**)&dinv,   g_dinv);
    cudaGetSymbolAddress((void**)&cnt,    g_cnt);
    cudaGetSymbolAddress((void**)&rowptr, g_rowptr);
    cudaGetSymbolAddress((void**)&nxt,    g_next);
    cudaGetSymbolAddress((void**)&csrc,   g_csrc);
    cudaGetSymbolAddress((void**)&cw,     g_cw);
    cudaGetSymbolAddress((void**)&Ahi,    g_Ahi);
    cudaGetSymbolAddress((void**)&Alo,    g_Alo);
    cudaGetSymbolAddress((void**)&Bhi,    g_Bhi);
    cudaGetSymbolAddress((void**)&Blo,    g_Blo);
    cudaGetSymbolAddress((void**)&Whi,    g_Whi);
    cudaGetSymbolAddress((void**)&Wlo,    g_Wlo);

    const int MT = (NNODES + 127) / 128;
    constexpr int SMEM256 = (256 + 512) * 64 * 4;   // 196608
    constexpr int SMEM128 = (256 + 256) * 64 * 4;   // 131072
    static bool attr_set = false;
    if (!attr_set) {
        cudaFuncSetAttribute(gemm3_kernel<256>, cudaFuncAttributeMaxDynamicSharedMemorySize, SMEM256);
        cudaFuncSetAttribute(gemm3_kernel<128>, cudaFuncAttributeMaxDynamicSharedMemorySize, SMEM128);
        attr_set = true;
    }

    // ---- CSR build + dinv (blocked scan) ----
    zeroi_kernel<<<(NNODES + 255) / 256, 256>>>(cnt, NNODES);
    hist_kernel<<<(E + 255) / 256, 256>>>(dst, cnt, E);
    scan1_kernel<<<NSB, 1024>>>(cnt, rowptr, dinv);
    scan2_kernel<<<1, 1>>>(rowptr);
    scan3_kernel<<<NSB, 1024>>>(rowptr, nxt);
    fill_kernel<<<(E + 255) / 256, 256>>>(src, dst, dinv, nxt, csrc, cw, E);

    float* out_h = (float*)d_out;                          // [N,192]
    float* out_o = (float*)d_out + (size_t)NNODES * 192;   // [N,5]

    auto run_wconv = [&](const float* Wp, int K, int N) {
        wconv_kernel<<<(K * N + 255) / 256, 256>>>(Wp, Whi, Wlo, K, N);
    };
    auto run_gemm = [&](const __nv_bfloat16* aHi, const __nv_bfloat16* aLo,
                        float* Cf, __nv_bfloat16* eHi, __nv_bfloat16* eLo,
                        const float* bias, int relu, int K, int N) {
        if (N % 256 == 0) {
            dim3 grid(N / 256, MT);
            gemm3_kernel<256><<<grid, 256, SMEM256>>>(aHi, aLo, Whi, Wlo, Cf, eHi, eLo,
                                                      bias, NNODES, K, N, relu);
        } else {
            dim3 grid((N + 127) / 128, MT);
            gemm3_kernel<128><<<grid, 256, SMEM128>>>(aHi, aLo, Whi, Wlo, Cf, eHi, eLo,
                                                      bias, NNODES, K, N, relu);
        }
    };
    // Column-chunked gather: 768-wide inputs run as two 384-column passes so
    // each pass's input slice (75 MB) stays L2-resident.
    auto run_gather = [&](const float* h, const float* bias, float* outf,
                          __nv_bfloat16* hi, __nv_bfloat16* lo, int F, int relu) {
        if (F == 768) {
            gather_kernel<<<NNODES, 96>>>(h, bias, outf, hi, lo, F, 0,   relu);
            gather_kernel<<<NNODES, 96>>>(h, bias, outf, hi, lo, F, 384, relu);
        } else {
            gather_kernel<<<NNODES, F / 4>>>(h, bias, outf, hi, lo, F, 0, relu);
        }
    };

    // ---- Layer 1: aggregate FIRST on width 768 (A(xW) == (Ax)W) -> split ----
    run_gather(x, nullptr, nullptr, Ahi, Alo, 768, 0);
    run_wconv(W[0], 768, 1536);
    run_gemm(Ahi, Alo, nullptr, Bhi, Blo, b[0], 1, 768, 1536);   // (Bhi,Blo) = h1

    // ---- Layer 2 ----
    run_wconv(W[1], 1536, 768);
    run_gemm(Bhi, Blo, B1, nullptr, nullptr, nullptr, 0, 1536, 768);   // B1 = h1 W2
    run_gather(B1, b[1], nullptr, Ahi, Alo, 768, 1);                   // (Ahi,Alo) = h2

    // ---- Layer 3 ----
    run_wconv(W[2], 768, 384);
    run_gemm(Ahi, Alo, B1, nullptr, nullptr, nullptr, 0, 768, 384);
    run_gather(B1, b[2], nullptr, Bhi, Blo, 384, 1);                   // (Bhi,Blo) = h3

    // ---- Layer 4 (fp32 h4 straight into out_h) ----
    run_wconv(W[3], 384, 192);
    run_gemm(Bhi, Blo, B1, nullptr, nullptr, nullptr, 0, 384, 192);
    run_gather(B1, b[3], out_h, nullptr, nullptr, 192, 1);             // out_h = h4

    // ---- Layer 5: Ahat(h4 W5) + b5 == (Ahat h4) W5 + b5 ----
    run_gather(out_h, nullptr, B0, nullptr, nullptr, 192, 0);          // B0 = Ahat h4
    out5_kernel<<<(NNODES + 255) / 256, 256>>>(B0, W[4], b[4], out_o);
}

// round 17
// speedup vs baseline: 1.0780x; 1.0780x over previous
#include <cuda_runtime.h>
#include <cuda_bf16.h>
#include <cstdint>

// ---------------------------------------------------------------------------
// Problem constants (fixed by the dataset)
// ---------------------------------------------------------------------------
#define NNODES 50000
#define MAXF   1536
#define MAXE   400000
#define NSB    ((NNODES + 1023) / 1024)

// Scratch (allocation-free: __device__ globals)
__device__ float g_B0[(size_t)NNODES * MAXF];
__device__ float g_B1[(size_t)NNODES * MAXF];
__device__ __nv_bfloat16 g_Ahi[(size_t)NNODES * MAXF];
__device__ __nv_bfloat16 g_Alo[(size_t)NNODES * MAXF];
__device__ __nv_bfloat16 g_Bhi[(size_t)NNODES * MAXF];
__device__ __nv_bfloat16 g_Blo[(size_t)NNODES * MAXF];
__device__ __nv_bfloat16 g_Whi[(size_t)MAXF * MAXF];
__device__ __nv_bfloat16 g_Wlo[(size_t)MAXF * MAXF];
__device__ float g_dinv[NNODES];
__device__ int   g_cnt[NNODES];
__device__ int   g_rowptr[NNODES + 1];
__device__ int   g_next[NNODES];
__device__ int   g_csrc[MAXE];
__device__ float g_cw[MAXE];
__device__ int   g_btot[64];

__device__ __forceinline__ uint32_t smem_u32(const void* p) {
    uint32_t a;
    asm("{ .reg .u64 t; cvta.to.shared.u64 t, %1; cvt.u32.u64 %0, t; }" : "=r"(a) : "l"(p));
    return a;
}

// ---------------------------------------------------------------------------
// CSR build
// ---------------------------------------------------------------------------
__global__ void zeroi_kernel(int* __restrict__ p, int n) {
    int i = blockIdx.x * blockDim.x + threadIdx.x;
    if (i < n) p[i] = 0;
}

__global__ void hist_kernel(const int* __restrict__ dst, int* __restrict__ cnt, int E) {
    int e = blockIdx.x * blockDim.x + threadIdx.x;
    if (e < E) atomicAdd(&cnt[dst[e]], 1);
}

// Blocked scan, pass 1: per-block exclusive scan, block totals, dinv.
__global__ __launch_bounds__(1024) void scan1_kernel(const int* __restrict__ cnt,
                                                     int* __restrict__ excl,
                                                     float* __restrict__ dinv) {
    __shared__ int wsum[32];
    const int tid = threadIdx.x, lane = tid & 31, wid = tid >> 5;
    const int i = blockIdx.x * 1024 + tid;
    int v = (i < NNODES) ? cnt[i] : 0;
    if (i < NNODES) dinv[i] = rsqrtf((float)v + 1.0f);
    int x = v;
    #pragma unroll
    for (int off = 1; off < 32; off <<= 1) {
        int t = __shfl_up_sync(0xFFFFFFFFu, x, off);
        if (lane >= off) x += t;
    }
    if (lane == 31) wsum[wid] = x;
    __syncthreads();
    if (wid == 0) {
        int y = wsum[lane];
        #pragma unroll
        for (int off = 1; off < 32; off <<= 1) {
            int t = __shfl_up_sync(0xFFFFFFFFu, y, off);
            if (lane >= off) y += t;
        }
        wsum[lane] = y;
    }
    __syncthreads();
    const int woff = (wid > 0) ? wsum[wid - 1] : 0;
    if (i < NNODES) excl[i] = x + woff - v;
    if (tid == 1023) g_btot[blockIdx.x] = x + woff;
}

// pass 2: scan the NSB block totals (tiny), write rowptr[NNODES]
__global__ void scan2_kernel(int* __restrict__ rowptr) {
    int run = 0;
    for (int b = 0; b < NSB; b++) { int t = g_btot[b]; g_btot[b] = run; run += t; }
    rowptr[NNODES] = run;
}

// pass 3: add block offsets, produce rowptr + next
__global__ __launch_bounds__(1024) void scan3_kernel(int* __restrict__ rowptr,
                                                     int* __restrict__ nxt) {
    const int i = blockIdx.x * 1024 + threadIdx.x;
    if (i < NNODES) {
        int v = rowptr[i] + g_btot[blockIdx.x];
        rowptr[i] = v;
        nxt[i] = v;
    }
}

__global__ void fill_kernel(const int* __restrict__ src, const int* __restrict__ dst,
                            const float* __restrict__ dinv, int* __restrict__ nxt,
                            int* __restrict__ csrc, float* __restrict__ cw, int E) {
    int e = blockIdx.x * blockDim.x + threadIdx.x;
    if (e >= E) return;
    int s = src[e], d = dst[e];
    int pos = atomicAdd(&nxt[d], 1);
    csrc[pos] = s;
    cw[pos] = dinv[s] * dinv[d];
}

// ---------------------------------------------------------------------------
// bf16 split helpers
// ---------------------------------------------------------------------------
__device__ __forceinline__ void store_split4_cs(__nv_bfloat16* hi, __nv_bfloat16* lo,
                                                size_t idx, float4 a) {
    __nv_bfloat16 h0 = __float2bfloat16(a.x), h1 = __float2bfloat16(a.y);
    __nv_bfloat16 h2 = __float2bfloat16(a.z), h3 = __float2bfloat16(a.w);
    __nv_bfloat16 l0 = __float2bfloat16(a.x - __bfloat162float(h0));
    __nv_bfloat16 l1 = __float2bfloat16(a.y - __bfloat162float(h1));
    __nv_bfloat16 l2 = __float2bfloat16(a.z - __bfloat162float(h2));
    __nv_bfloat16 l3 = __float2bfloat16(a.w - __bfloat162float(h3));
    __nv_bfloat162 hv0 = __halves2bfloat162(h0, h1), hv1 = __halves2bfloat162(h2, h3);
    __nv_bfloat162 lv0 = __halves2bfloat162(l0, l1), lv1 = __halves2bfloat162(l2, l3);
    asm volatile("st.global.cs.v2.b32 [%0], {%1,%2};"
                 :: "l"(hi + idx), "r"(*(uint32_t*)&hv0), "r"(*(uint32_t*)&hv1) : "memory");
    asm volatile("st.global.cs.v2.b32 [%0], {%1,%2};"
                 :: "l"(lo + idx), "r"(*(uint32_t*)&lv0), "r"(*(uint32_t*)&lv1) : "memory");
}

__device__ __forceinline__ void store_split2(__nv_bfloat16* hi, __nv_bfloat16* lo,
                                             size_t idx, float a, float b) {
    __nv_bfloat16 h0 = __float2bfloat16(a), h1 = __float2bfloat16(b);
    __nv_bfloat16 l0 = __float2bfloat16(a - __bfloat162float(h0));
    __nv_bfloat16 l1 = __float2bfloat16(b - __bfloat162float(h1));
    __nv_bfloat162 hv = __halves2bfloat162(h0, h1);
    __nv_bfloat162 lv = __halves2bfloat162(l0, l1);
    *(uint32_t*)(hi + idx) = *(uint32_t*)&hv;
    *(uint32_t*)(lo + idx) = *(uint32_t*)&lv;
}

// ---------------------------------------------------------------------------
// Fused CSR gather over a column chunk: one node per block,
// blockDim = chunkwidth/4, columns [fbase, fbase + 4*blockDim).
// ---------------------------------------------------------------------------
__global__ void gather_kernel(const float* __restrict__ h, const float* __restrict__ bias,
                              float* __restrict__ outf,
                              __nv_bfloat16* __restrict__ hi, __nv_bfloat16* __restrict__ lo,
                              int F, int fbase, int do_relu)
{
    const int node = blockIdx.x;
    const int f0 = fbase + threadIdx.x * 4;
    const int rs = g_rowptr[node], re = g_rowptr[node + 1];
    const float di = g_dinv[node];
    const float d2 = di * di;

    float4 acc = *(const float4*)(h + (size_t)node * F + f0);
    acc.x *= d2; acc.y *= d2; acc.z *= d2; acc.w *= d2;
    if (bias) {
        float4 bb = *(const float4*)(bias + f0);
        acc.x += bb.x; acc.y += bb.y; acc.z += bb.z; acc.w += bb.w;
    }
    for (int e = rs; e < re; e++) {
        const int s = g_csrc[e];
        const float w = g_cw[e];
        float4 v = *(const float4*)(h + (size_t)s * F + f0);
        acc.x += v.x * w; acc.y += v.y * w; acc.z += v.z * w; acc.w += v.w * w;
    }
    if (do_relu) {
        acc.x = fmaxf(acc.x, 0.f); acc.y = fmaxf(acc.y, 0.f);
        acc.z = fmaxf(acc.z, 0.f); acc.w = fmaxf(acc.w, 0.f);
    }
    const size_t idx = (size_t)node * F + f0;
    if (outf) {
        asm volatile("st.global.cs.v4.f32 [%0], {%1,%2,%3,%4};"
                     :: "l"(outf + idx), "f"(acc.x), "f"(acc.y), "f"(acc.z), "f"(acc.w)
                     : "memory");
    }
    if (hi) store_split4_cs(hi, lo, idx, acc);
}

// ---------------------------------------------------------------------------
// W [K,N] fp32 -> Wt_hi/Wt_lo [N,K] bf16 (transpose + split)
// ---------------------------------------------------------------------------
__global__ void wconv_kernel(const float* __restrict__ W, __nv_bfloat16* __restrict__ Thi,
                             __nv_bfloat16* __restrict__ Tlo, int K, int N) {
    int idx = blockIdx.x * blockDim.x + threadIdx.x;
    if (idx >= K * N) return;
    int k = idx / N, n = idx - k * N;
    float w = W[idx];
    __nv_bfloat16 h = __float2bfloat16(w);
    Thi[(size_t)n * K + k] = h;
    Tlo[(size_t)n * K + k] = __float2bfloat16(w - __bfloat162float(h));
}

// ---------------------------------------------------------------------------
// Final layer: out[node, 0..4] = g[node, :] @ W5[192,5] + b5  (thread per node)
// ---------------------------------------------------------------------------
__global__ __launch_bounds__(256) void out5_kernel(const float* __restrict__ g,
                                                   const float* __restrict__ W5,
                                                   const float* __restrict__ b5,
                                                   float* __restrict__ out)
{
    __shared__ float sW[192 * 5];
    for (int i = threadIdx.x; i < 192 * 5; i += 256) sW[i] = W5[i];
    __syncthreads();
    const int node = blockIdx.x * 256 + threadIdx.x;
    if (node >= NNODES) return;
    float a0 = b5[0], a1 = b5[1], a2 = b5[2], a3 = b5[3], a4 = b5[4];
    const float4* gp = (const float4*)(g + (size_t)node * 192);
    #pragma unroll 4
    for (int k4 = 0; k4 < 48; k4++) {
        float4 v = gp[k4];
        const float* w = &sW[(k4 * 4) * 5];
        a0 += v.x * w[0] + v.y * w[5] + v.z * w[10] + v.w * w[15];
        a1 += v.x * w[1] + v.y * w[6] + v.z * w[11] + v.w * w[16];
        a2 += v.x * w[2] + v.y * w[7] + v.z * w[12] + v.w * w[17];
        a3 += v.x * w[3] + v.y * w[8] + v.z * w[13] + v.w * w[18];
        a4 += v.x * w[4] + v.y * w[9] + v.z * w[14] + v.w * w[19];
    }
    float* op = out + (size_t)node * 5;
    op[0] = a0; op[1] = a1; op[2] = a2; op[3] = a3; op[4] = a4;
}

// ---------------------------------------------------------------------------
// Fused bf16x3 GEMM: C = Ahi*Whi + Alo*Whi + Ahi*Wlo, all 3 passes per chunk.
//   Block tile 128 x BNT x 64 (BK=64), 2-stage cp.async pipeline.
//   (Reverted to the measured-best R12 configuration; BK=32/4-stage regressed.)
//   Optional epilogue: out = relu(acc + bias) -> bf16 hi/lo split buffers.
// ---------------------------------------------------------------------------
template<int BNT>
__global__ __launch_bounds__(256)
void gemm3_kernel(const __nv_bfloat16* __restrict__ Ahi, const __nv_bfloat16* __restrict__ Alo,
                  const __nv_bfloat16* __restrict__ Whi, const __nv_bfloat16* __restrict__ Wlo,
                  float* __restrict__ Cf,
                  __nv_bfloat16* __restrict__ Ehi, __nv_bfloat16* __restrict__ Elo,
                  const float* __restrict__ bias,
                  int M, int K, int N, int do_relu)
{
    constexpr int NW = BNT / 32;
    constexpr int STAGE = (256 + 2 * BNT) * 128;    // BK=64 -> 128B rows
    constexpr int OFF_ALO = 128 * 128;
    constexpr int OFF_BHI = 256 * 128;
    constexpr int OFF_BLO = (256 + BNT) * 128;
    constexpr int NCH = (256 + 2 * BNT) * 8 / 256;

    extern __shared__ __align__(1024) char smem[];
    const uint32_t sbase = smem_u32(smem);

    const int tid = threadIdx.x, lane = tid & 31, wid = tid >> 5;
    const int wm = (wid & 1) * 64;
    const int wn = (wid >> 1) * (BNT / 4);
    const int m0 = blockIdx.y * 128;
    const int n0 = blockIdx.x * BNT;
    const int kc = K / 64;

    float acc[4][NW][4];
    #pragma unroll
    for (int mi = 0; mi < 4; mi++)
        #pragma unroll
        for (int ni = 0; ni < NW; ni++)
            #pragma unroll
            for (int q = 0; q < 4; q++) acc[mi][ni][q] = 0.f;

    auto issue = [&](int c) {
        const int st = c & 1;
        const int kk = c * 64;
        const uint32_t dstb = sbase + (uint32_t)st * STAGE;
        #pragma unroll
        for (int h = 0; h < NCH; h++) {
            const int idx = tid + h * 256;
            const int r_all = idx >> 3, ch = idx & 7;
            const __nv_bfloat16* base;
            uint32_t roff;
            int r, grow, limit;
            if (r_all < 128)            { base = Ahi; roff = 0;       r = r_all;             grow = m0 + r; limit = M; }
            else if (r_all < 256)       { base = Alo; roff = OFF_ALO; r = r_all - 128;       grow = m0 + r; limit = M; }
            else if (r_all < 256 + BNT) { base = Whi; roff = OFF_BHI; r = r_all - 256;       grow = n0 + r; limit = N; }
            else                        { base = Wlo; roff = OFF_BLO; r = r_all - 256 - BNT; grow = n0 + r; limit = N; }
            const int ok = (grow < limit) ? 16 : 0;
            const int grc = ok ? grow : 0;
            const void* g = base + (size_t)grc * K + kk + ch * 8;
            const uint32_t d = dstb + roff + (uint32_t)r * 128 + (uint32_t)((ch ^ (r & 7)) * 16);
            asm volatile("cp.async.cg.shared.global [%0], [%1], 16, %2;"
                         :: "r"(d), "l"(g), "r"(ok));
        }
        asm volatile("cp.async.commit_group;" ::: "memory");
    };

    auto compute = [&](int st) {
        const uint32_t sAh = sbase + (uint32_t)st * STAGE;
        const uint32_t sAl = sAh + OFF_ALO;
        const uint32_t sBh = sAh + OFF_BHI;
        const uint32_t sBl = sAh + OFF_BLO;
        #pragma unroll
        for (int ks = 0; ks < 4; ks++) {
            uint32_t ah[4][4], al[4][4], b[NW][2];
            #pragma unroll
            for (int mi = 0; mi < 4; mi++) {
                const int r = wm + mi * 16 + (lane & 15);
                const int ch = ks * 2 + (lane >> 4);
                const uint32_t off = (uint32_t)r * 128 + (uint32_t)((ch ^ (r & 7)) * 16);
                asm volatile("ldmatrix.sync.aligned.m8n8.x4.shared.b16 {%0,%1,%2,%3}, [%4];"
                             : "=r"(ah[mi][0]), "=r"(ah[mi][1]), "=r"(ah[mi][2]), "=r"(ah[mi][3])
                             : "r"(sAh + off));
                asm volatile("ldmatrix.sync.aligned.m8n8.x4.shared.b16 {%0,%1,%2,%3}, [%4];"
                             : "=r"(al[mi][0]), "=r"(al[mi][1]), "=r"(al[mi][2]), "=r"(al[mi][3])
                             : "r"(sAl + off));
            }
            #pragma unroll
            for (int g2 = 0; g2 < NW / 2; g2++) {
                const int r = wn + g2 * 16 + (lane & 7) + ((lane >> 4) << 3);
                const int ch = ks * 2 + ((lane >> 3) & 1);
                const uint32_t off = (uint32_t)r * 128 + (uint32_t)((ch ^ (r & 7)) * 16);
                asm volatile("ldmatrix.sync.aligned.m8n8.x4.shared.b16 {%0,%1,%2,%3}, [%4];"
                             : "=r"(b[g2 * 2][0]), "=r"(b[g2 * 2][1]),
                               "=r"(b[g2 * 2 + 1][0]), "=r"(b[g2 * 2 + 1][1])
                             : "r"(sBh + off));
            }
            #pragma unroll
            for (int mi = 0; mi < 4; mi++)
                #pragma unroll
                for (int ni = 0; ni < NW; ni++) {
                    asm volatile(
                        "mma.sync.aligned.m16n8k16.row.col.f32.bf16.bf16.f32 "
                        "{%0,%1,%2,%3}, {%4,%5,%6,%7}, {%8,%9}, {%0,%1,%2,%3};"
                        : "+f"(acc[mi][ni][0]), "+f"(acc[mi][ni][1]),
                          "+f"(acc[mi][ni][2]), "+f"(acc[mi][ni][3])
                        : "r"(ah[mi][0]), "r"(ah[mi][1]), "r"(ah[mi][2]), "r"(ah[mi][3]),
                          "r"(b[ni][0]), "r"(b[ni][1]));
                }
            #pragma unroll
            for (int mi = 0; mi < 4; mi++)
                #pragma unroll
                for (int ni = 0; ni < NW; ni++) {
                    asm volatile(
                        "mma.sync.aligned.m16n8k16.row.col.f32.bf16.bf16.f32 "
                        "{%0,%1,%2,%3}, {%4,%5,%6,%7}, {%8,%9}, {%0,%1,%2,%3};"
                        : "+f"(acc[mi][ni][0]), "+f"(acc[mi][ni][1]),
                          "+f"(acc[mi][ni][2]), "+f"(acc[mi][ni][3])
                        : "r"(al[mi][0]), "r"(al[mi][1]), "r"(al[mi][2]), "r"(al[mi][3]),
                          "r"(b[ni][0]), "r"(b[ni][1]));
                }
            #pragma unroll
            for (int g2 = 0; g2 < NW / 2; g2++) {
                const int r = wn + g2 * 16 + (lane & 7) + ((lane >> 4) << 3);
                const int ch = ks * 2 + ((lane >> 3) & 1);
                const uint32_t off = (uint32_t)r * 128 + (uint32_t)((ch ^ (r & 7)) * 16);
                asm volatile("ldmatrix.sync.aligned.m8n8.x4.shared.b16 {%0,%1,%2,%3}, [%4];"
                             : "=r"(b[g2 * 2][0]), "=r"(b[g2 * 2][1]),
                               "=r"(b[g2 * 2 + 1][0]), "=r"(b[g2 * 2 + 1][1])
                             : "r"(sBl + off));
            }
            #pragma unroll
            for (int mi = 0; mi < 4; mi++)
                #pragma unroll
                for (int ni = 0; ni < NW; ni++) {
                    asm volatile(
                        "mma.sync.aligned.m16n8k16.row.col.f32.bf16.bf16.f32 "
                        "{%0,%1,%2,%3}, {%4,%5,%6,%7}, {%8,%9}, {%0,%1,%2,%3};"
                        : "+f"(acc[mi][ni][0]), "+f"(acc[mi][ni][1]),
                          "+f"(acc[mi][ni][2]), "+f"(acc[mi][ni][3])
                        : "r"(ah[mi][0]), "r"(ah[mi][1]), "r"(ah[mi][2]), "r"(ah[mi][3]),
                          "r"(b[ni][0]), "r"(b[ni][1]));
                }
        }
    };

    issue(0);
    if (kc > 1) issue(1);
    for (int c = 0; c < kc; c++) {
        if (c + 1 < kc) {
            asm volatile("cp.async.wait_group 1;" ::: "memory");
        } else {
            asm volatile("cp.async.wait_group 0;" ::: "memory");
        }
        __syncthreads();
        compute(c & 1);
        __syncthreads();
        if (c + 2 < kc) issue(c + 2);
    }

    // epilogue
    #pragma unroll
    for (int mi = 0; mi < 4; mi++) {
        const int r0 = m0 + wm + mi * 16 + (lane >> 2);
        #pragma unroll
        for (int ni = 0; ni < NW; ni++) {
            const int col = n0 + wn + ni * 8 + 2 * (lane & 3);
            if (col >= N) continue;
            float bx = 0.f, by = 0.f;
            if (bias) { float2 bb = *(const float2*)(bias + col); bx = bb.x; by = bb.y; }
            #pragma unroll
            for (int half = 0; half < 2; half++) {
                const int r = r0 + half * 8;
                if (r >= M) continue;
                float vx = acc[mi][ni][half * 2 + 0] + bx;
                float vy = acc[mi][ni][half * 2 + 1] + by;
                if (do_relu) { vx = fmaxf(vx, 0.f); vy = fmaxf(vy, 0.f); }
                const size_t idx = (size_t)r * N + col;
                if (Cf) *(float2*)(Cf + idx) = make_float2(vx, vy);
                if (Ehi) store_split2(Ehi, Elo, idx, vx, vy);
            }
        }
    }
}

// ---------------------------------------------------------------------------
// kernel_launch
// ---------------------------------------------------------------------------
extern "C" void kernel_launch(void* const* d_in, const int* in_sizes, int n_in,
                              void* d_out, int out_size)
{
    const float* x   = (const float*)d_in[0];
    const int*   ei  = (const int*)d_in[1];
    const int    E   = in_sizes[1] / 2;
    const int*   src = ei;
    const int*   dst = ei + E;

    const float* W[5];
    const float* b[5];
    for (int i = 0; i < 5; i++) {
        W[i] = (const float*)d_in[2 + 2 * i];
        b[i] = (const float*)d_in[3 + 2 * i];
    }

    float *B0, *B1, *dinv, *cw;
    int *cnt, *rowptr, *nxt, *csrc;
    __nv_bfloat16 *Ahi, *Alo, *Bhi, *Blo, *Whi, *Wlo;
    cudaGetSymbolAddress((void**)&B0,     g_B0);
    cudaGetSymbolAddress((void**)&B1,     g_B1);
    cudaGetSymbolAddress((void**)&dinv,   g_dinv);
    cudaGetSymbolAddress((void**)&cnt,    g_cnt);
    cudaGetSymbolAddress((void**)&rowptr, g_rowptr);
    cudaGetSymbolAddress((void**)&nxt,    g_next);
    cudaGetSymbolAddress((void**)&csrc,   g_csrc);
    cudaGetSymbolAddress((void**)&cw,     g_cw);
    cudaGetSymbolAddress((void**)&Ahi,    g_Ahi);
    cudaGetSymbolAddress((void**)&Alo,    g_Alo);
    cudaGetSymbolAddress((void**)&Bhi,    g_Bhi);
    cudaGetSymbolAddress((void**)&Blo,    g_Blo);
    cudaGetSymbolAddress((void**)&Whi,    g_Whi);
    cudaGetSymbolAddress((void**)&Wlo,    g_Wlo);

    const int MT = (NNODES + 127) / 128;
    constexpr int SMEM256 = (256 + 512) * 128 * 2;   // 196608
    constexpr int SMEM128 = (256 + 256) * 128 * 2;   // 131072
    static bool attr_set = false;
    if (!attr_set) {
        cudaFuncSetAttribute(gemm3_kernel<256>, cudaFuncAttributeMaxDynamicSharedMemorySize, SMEM256);
        cudaFuncSetAttribute(gemm3_kernel<128>, cudaFuncAttributeMaxDynamicSharedMemorySize, SMEM128);
        attr_set = true;
    }

    // ---- CSR build + dinv (blocked scan) ----
    zeroi_kernel<<<(NNODES + 255) / 256, 256>>>(cnt, NNODES);
    hist_kernel<<<(E + 255) / 256, 256>>>(dst, cnt, E);
    scan1_kernel<<<NSB, 1024>>>(cnt, rowptr, dinv);
    scan2_kernel<<<1, 1>>>(rowptr);
    scan3_kernel<<<NSB, 1024>>>(rowptr, nxt);
    fill_kernel<<<(E + 255) / 256, 256>>>(src, dst, dinv, nxt, csrc, cw, E);

    float* out_h = (float*)d_out;                          // [N,192]
    float* out_o = (float*)d_out + (size_t)NNODES * 192;   // [N,5]

    auto run_wconv = [&](const float* Wp, int K, int N) {
        wconv_kernel<<<(K * N + 255) / 256, 256>>>(Wp, Whi, Wlo, K, N);
    };
    auto run_gemm = [&](const __nv_bfloat16* aHi, const __nv_bfloat16* aLo,
                        float* Cf, __nv_bfloat16* eHi, __nv_bfloat16* eLo,
                        const float* bias, int relu, int K, int N) {
        if (N % 256 == 0) {
            dim3 grid(N / 256, MT);
            gemm3_kernel<256><<<grid, 256, SMEM256>>>(aHi, aLo, Whi, Wlo, Cf, eHi, eLo,
                                                      bias, NNODES, K, N, relu);
        } else {
            dim3 grid((N + 127) / 128, MT);
            gemm3_kernel<128><<<grid, 256, SMEM128>>>(aHi, aLo, Whi, Wlo, Cf, eHi, eLo,
                                                      bias, NNODES, K, N, relu);
        }
    };
    // Column-chunked gather: chunk width chosen so each pass's input slice
    // (NNODES * chunk * 4 B) has L2 headroom: 768 -> 3x256 (50 MB),
    // 384 -> 2x192 (38 MB), 192 -> single pass (38 MB).
    auto run_gather = [&](const float* h, const float* bias, float* outf,
                          __nv_bfloat16* hi, __nv_bfloat16* lo, int F, int relu) {
        int cw_cols = (F == 768) ? 256 : (F == 384) ? 192 : F;
        for (int fb = 0; fb < F; fb += cw_cols)
            gather_kernel<<<NNODES, cw_cols / 4>>>(h, bias, outf, hi, lo, F, fb, relu);
    };

    // ---- Layer 1: aggregate FIRST on width 768 (A(xW) == (Ax)W) -> split ----
    run_gather(x, nullptr, nullptr, Ahi, Alo, 768, 0);
    run_wconv(W[0], 768, 1536);
    run_gemm(Ahi, Alo, nullptr, Bhi, Blo, b[0], 1, 768, 1536);   // (Bhi,Blo) = h1

    // ---- Layer 2 ----
    run_wconv(W[1], 1536, 768);
    run_gemm(Bhi, Blo, B1, nullptr, nullptr, nullptr, 0, 1536, 768);   // B1 = h1 W2
    run_gather(B1, b[1], nullptr, Ahi, Alo, 768, 1);                   // (Ahi,Alo) = h2

    // ---- Layer 3 ----
    run_wconv(W[2], 768, 384);
    run_gemm(Ahi, Alo, B1, nullptr, nullptr, nullptr, 0, 768, 384);
    run_gather(B1, b[2], nullptr, Bhi, Blo, 384, 1);                   // (Bhi,Blo) = h3

    // ---- Layer 4 (fp32 h4 straight into out_h) ----
    run_wconv(W[3], 384, 192);
    run_gemm(Bhi, Blo, B1, nullptr, nullptr, nullptr, 0, 384, 192);
    run_gather(B1, b[3], out_h, nullptr, nullptr, 192, 1);             // out_h = h4

    // ---- Layer 5: Ahat(h4 W5) + b5 == (Ahat h4) W5 + b5 ----
    run_gather(out_h, nullptr, B0, nullptr, nullptr, 192, 0);          // B0 = Ahat h4
    out5_kernel<<<(NNODES + 255) / 256, 256>>>(B0, W[4], b[4], out_o);
}